// round 12
// baseline (speedup 1.0000x reference)
#include <cuda_runtime.h>
#include <cuda_bf16.h>
#include <cstdint>

#define T_LEN 2048
#define EMB   256
#define H2    256
#define G4    1024
#define C_TAGS 12
#define NEGV  (-10000.0f)
#define START_TAG 10
#define STOP_TAG  11

// stamped h exchange buffer:
//   sbuf[2 bufs][8 sources][17 x 16B]  (16 entries + 16B pad per source)
//   entry (S,w) = { h[S*32+2w], h[S*32+2w+1], stamp, pad }
// 272B source stride => LDS wavefronts conflict-free (bank shift 4/source)
#define SRC_STRIDE_B 272
#define BUF_STRIDE_B 2176   // 8 * 272

// ---------------------------------------------------------------- scratch
__device__ float g_pre[2][T_LEN][G4];    // 16 MB: gate pre-activations
__device__ float g_hs[2][T_LEN][H2];     // 4 MB: hidden states per direction
__device__ float g_feats[T_LEN][C_TAGS]; // 96 KB

__device__ __forceinline__ uint32_t smem_u32(const void* p) {
    return (uint32_t)__cvta_generic_to_shared(p);
}

__device__ __forceinline__ float fast_sig(float x) {
    return __fdividef(1.0f, 1.0f + __expf(-x));
}
__device__ __forceinline__ float fast_tanh(float x) {
    return __fdividef(2.0f, 1.0f + __expf(-2.0f * x)) - 1.0f;
}

__device__ __forceinline__ void fma2(uint64_t& d, uint64_t a, uint64_t b) {
    asm("fma.rn.f32x2 %0, %1, %2, %0;" : "+l"(d) : "l"(a), "l"(b));
}
__device__ __forceinline__ float unpack_sum(uint64_t a) {
    float lo, hi;
    asm("mov.b64 {%0, %1}, %2;" : "=f"(lo), "=f"(hi) : "l"(a));
    return lo + hi;
}

// dummy kernel: shifts ncu's fixed capture slot onto lstm_rec
__global__ void nop_kernel() {}

// ============================================================ Phase 1: GEMM
__global__ void gates_gemm(const int* __restrict__ sent,
                           const float* __restrict__ emb,
                           const float* __restrict__ Wih_f,
                           const float* __restrict__ bih_f,
                           const float* __restrict__ bhh_f,
                           const float* __restrict__ Wih_b,
                           const float* __restrict__ bih_b,
                           const float* __restrict__ bhh_b)
{
    const int dir = blockIdx.z;
    const float* Wih = dir ? Wih_b : Wih_f;
    const float* bih = dir ? bih_b : bih_f;
    const float* bhh = dir ? bhh_b : bhh_f;
    const int t0 = blockIdx.x * 32;
    const int r0 = blockIdx.y * 32;
    const int tid = threadIdx.x;
    const int lane = tid & 31;
    const int warp = tid >> 5;

    __shared__ float Xs[32][33];
    __shared__ float Ws[32][33];
    __shared__ int   sidx[32];

    if (tid < 32) sidx[tid] = sent[t0 + tid];
    __syncthreads();

    float acc[4] = {0.f, 0.f, 0.f, 0.f};
    for (int kc = 0; kc < EMB; kc += 32) {
        #pragma unroll
        for (int e = 0; e < 4; e++) {
            int idx = tid + 256 * e;
            int a = idx >> 5, b = idx & 31;
            Xs[a][b] = emb[(long long)sidx[a] * EMB + kc + b];
            Ws[a][b] = Wih[(r0 + a) * EMB + kc + b];
        }
        __syncthreads();
        #pragma unroll
        for (int k = 0; k < 32; k++) {
            float wk = Ws[lane][k];
            #pragma unroll
            for (int e = 0; e < 4; e++)
                acc[e] += Xs[warp + 8 * e][k] * wk;
        }
        __syncthreads();
    }
    float bias = bih[r0 + lane] + bhh[r0 + lane];
    #pragma unroll
    for (int e = 0; e < 4; e++)
        g_pre[dir][t0 + warp + 8 * e][r0 + lane] = acc[e] + bias;
}

// ====================================================== Phase 2: recurrence
// 2 clusters of 8 CTAs (one per direction). Warp w owns h-pair {2w,2w+1}
// end-to-end. NO mbarriers, NO standalone fences. Producer lane r: plain
// st.shared::cluster.v2 of (h0,h1), then st.release.cluster of the stamp
// (same lane => release orders the data store at the destination).
// Consumers poll the 128 stamps in their OWN smem with ld.acquire.cluster.
// Stamp(S,w)==it also proves warp (S,w) finished reading buf[(it-1)&1]
// (program order), so the stamps carry the backpressure.
__global__ void __cluster_dims__(8, 1, 1) __launch_bounds__(512, 1)
lstm_rec(const float* __restrict__ Whh_f,
         const float* __restrict__ Whh_b,
         const float* __restrict__ h0,
         const float* __restrict__ c0)
{
    const int dir  = blockIdx.x >> 3;
    unsigned rank;
    asm("mov.u32 %0, %%cluster_ctarank;" : "=r"(rank));
    const float* Whh = dir ? Whh_b : Whh_f;

    const int tid  = threadIdx.x;
    const int w    = tid >> 5;        // warp 0..15
    const int lane = tid & 31;
    const int g    = lane >> 3;       // gate 0..3 (i,f,g,o)
    const int hsel = (lane >> 2) & 1; // which h of the pair
    const int seg  = lane & 3;        // 64-col segment
    const int hidx = (int)rank * 32 + 2 * w + hsel;  // global h index
    const int row  = (g << 8) + hidx;                // gate row

    __shared__ __align__(16) uint32_t sbuf[2 * BUF_STRIDE_B / 4];

    // weights: 64 fp32 cols of my row -> 32 packed f32x2 regs.
    // w2[j] covers cols (seg*64 + 2j, +1)  == entry j's h pair. 1:1 match.
    uint64_t w2[32];
    {
        const ulonglong2* wp = (const ulonglong2*)(Whh + row * H2 + seg * 64);
        #pragma unroll
        for (int i = 0; i < 16; i++) {
            ulonglong2 v = wp[i];
            w2[2*i] = v.x; w2[2*i+1] = v.y;
        }
    }

    // init BOTH buffers: buf0 = h0 data + stamp 0; buf1 = stamp 0 too.
    // (buf0 polls expect even stamps >= 2, buf1 polls expect odd stamps
    //  >= 1, so stamp 0 can never false-trigger a poll. Round-11 bug:
    //  buf1 stamps were left uninitialized garbage.)
    for (int e = tid; e < 128; e += 512) {
        int S = e >> 4, wp = e & 15;
        uint32_t* ent0 = sbuf + (S * SRC_STRIDE_B + wp * 16) / 4;
        uint32_t* ent1 = ent0 + BUF_STRIDE_B / 4;
        ent0[0] = __float_as_uint(h0[dir * H2 + S * 32 + 2 * wp]);
        ent0[1] = __float_as_uint(h0[dir * H2 + S * 32 + 2 * wp + 1]);
        ent0[2] = 0u;  ent0[3] = 0u;
        ent1[0] = 0u;  ent1[1] = 0u;  ent1[2] = 0u;  ent1[3] = 0u;
    }
    float creg = 0.f;
    if (lane == 0 || lane == 4) creg = c0[dir * H2 + hidx];

    __syncthreads();
    asm volatile("barrier.cluster.arrive.aligned;" ::: "memory");
    asm volatile("barrier.cluster.wait.aligned;"  ::: "memory");

    const uint32_t sb = smem_u32(sbuf);
    // producer: lane r (<8) -> remote addr of entry (rank, w) in CTA r
    uint32_t rstore = 0;
    if (lane < 8) {
        uint32_t loc = sb + (uint32_t)((int)rank * SRC_STRIDE_B + w * 16);
        asm("mapa.shared::cluster.u32 %0, %1, %2;"
            : "=r"(rstore) : "r"(loc), "r"(lane));
    }
    // poll: lane covers entries e = lane*4 .. lane*4+3 (all same source)
    const uint32_t pbase = sb + (uint32_t)((lane >> 2) * SRC_STRIDE_B
                                           + (lane & 3) * 64 + 8);
    // dot: lane reads source blocks 2*seg and 2*seg+1
    const uint32_t dbase = sb + (uint32_t)(2 * seg * SRC_STRIDE_B);

    // pre-load step-0 pre-activation (seg==0 lanes)
    float gp = 0.f;
    if (seg == 0) gp = g_pre[dir][dir ? (T_LEN - 1) : 0][row];

    for (int it = 0; it < T_LEN; it++) {
        const uint32_t bufoff = (it & 1) ? (uint32_t)BUF_STRIDE_B : 0u;
        const int t = dir ? (T_LEN - 1 - it) : it;

        if (it > 0) {
            const uint32_t expv = (uint32_t)it;
            const uint32_t p = pbase + bufoff;
            unsigned rdy;
            do {
                uint32_t s0, s1, s2, s3;
                asm volatile("ld.acquire.cluster.shared::cta.u32 %0, [%1];"
                             : "=r"(s0) : "r"(p) : "memory");
                asm volatile("ld.acquire.cluster.shared::cta.u32 %0, [%1+16];"
                             : "=r"(s1) : "r"(p) : "memory");
                asm volatile("ld.acquire.cluster.shared::cta.u32 %0, [%1+32];"
                             : "=r"(s2) : "r"(p) : "memory");
                asm volatile("ld.acquire.cluster.shared::cta.u32 %0, [%1+48];"
                             : "=r"(s3) : "r"(p) : "memory");
                rdy = (s0 == expv) & (s1 == expv) & (s2 == expv) & (s3 == expv);
            } while (__ballot_sync(0xffffffffu, rdy) != 0xffffffffu);
        }

        // prefetch NEXT step's pre-activation (hidden behind this step)
        float gpn = 0.f;
        if (seg == 0 && it + 1 < T_LEN) {
            int tn = dir ? (T_LEN - 2 - it) : (it + 1);
            gpn = g_pre[dir][tn][row];
        }

        // 64-col dot: 32 LDS.64 h-pairs from two source blocks, 4 fma2 chains
        const uint32_t b0 = dbase + bufoff;
        uint64_t a0 = 0, a1 = 0, a2 = 0, a3 = 0;
        #pragma unroll
        for (int i = 0; i < 8; i++) {
            uint64_t p0, p1, p2, p3;
            asm volatile("ld.shared.b64 %0, [%1];" : "=l"(p0) : "r"(b0 + 32u*i));
            asm volatile("ld.shared.b64 %0, [%1];" : "=l"(p1) : "r"(b0 + 32u*i + 16u));
            asm volatile("ld.shared.b64 %0, [%1];" : "=l"(p2) : "r"(b0 + 272u + 32u*i));
            asm volatile("ld.shared.b64 %0, [%1];" : "=l"(p3) : "r"(b0 + 272u + 32u*i + 16u));
            fma2(a0, w2[2*i],      p0);
            fma2(a1, w2[2*i + 1],  p1);
            fma2(a2, w2[16 + 2*i], p2);
            fma2(a3, w2[17 + 2*i], p3);
        }
        float acc = (unpack_sum(a0) + unpack_sum(a1)) +
                    (unpack_sum(a2) + unpack_sum(a3));
        // reduce within 4-lane segment groups
        acc += __shfl_down_sync(0xffffffffu, acc, 2, 4);
        acc += __shfl_down_sync(0xffffffffu, acc, 1, 4);

        // nonlinearity at seg0 lanes (warp-uniform g per 8-lane group)
        float gatev = 0.f;
        if (seg == 0) {
            float raw = acc + gp;
            gatev = (g == 2) ? fast_tanh(raw) : fast_sig(raw);
        }
        gp = gpn;

        // gather i,f,g,o (lanes 0,8,16,24 -> lane 0; 4,12,20,28 -> lane 4)
        float d8  = __shfl_down_sync(0xffffffffu, gatev, 8);
        float d16 = __shfl_down_sync(0xffffffffu, gatev, 16);
        float d24 = __shfl_down_sync(0xffffffffu, gatev, 24);

        float h = 0.f;
        if (lane == 0 || lane == 4) {
            creg = d8 * creg + gatev * d16;      // F*c + I*G
            h = d24 * fast_tanh(creg);           // O * tanh(c)
            g_hs[dir][t][hidx] = h;
        }

        if (it < T_LEN - 1) {
            float hv0 = __shfl_sync(0xffffffffu, h, 0);
            float hv1 = __shfl_sync(0xffffffffu, h, 4);
            if (lane < 8) {
                const uint32_t nboff = ((it + 1) & 1) ? (uint32_t)BUF_STRIDE_B : 0u;
                const uint32_t da = rstore + nboff;
                // plain data store, then RELEASE stamp store from the SAME
                // lane: release orders this lane's prior data store at the
                // destination. No vector-atomicity assumption.
                asm volatile("st.shared::cluster.v2.f32 [%0], {%1, %2};"
                             :: "r"(da), "f"(hv0), "f"(hv1) : "memory");
                asm volatile("st.release.cluster.shared::cluster.u32 [%0], %1;"
                             :: "r"(da + 8u), "r"((uint32_t)(it + 1)) : "memory");
            }
        }
    }
}

// ========================================================= Phase 3: feats
__global__ void feats_kernel(const float* __restrict__ Wlin,
                             const float* __restrict__ blin)
{
    __shared__ float Wl[C_TAGS][512];
    const int tid = threadIdx.x;
    for (int i = tid; i < C_TAGS * 512; i += 256)
        Wl[i >> 9][i & 511] = Wlin[i];
    __syncthreads();

    const int warp = tid >> 5, lane = tid & 31;
    const int t = blockIdx.x * 8 + warp;

    float hv[16];
    #pragma unroll
    for (int i = 0; i < 8; i++) hv[i]     = g_hs[0][t][lane + 32 * i];
    #pragma unroll
    for (int i = 0; i < 8; i++) hv[8 + i] = g_hs[1][t][lane + 32 * i];

    #pragma unroll
    for (int c = 0; c < C_TAGS; c++) {
        float a = 0.f;
        #pragma unroll
        for (int i = 0; i < 16; i++)
            a += hv[i] * Wl[c][lane + 32 * i];
        #pragma unroll
        for (int o = 16; o; o >>= 1)
            a += __shfl_down_sync(0xffffffffu, a, o);
        if (lane == 0) g_feats[t][c] = a + blin[c];
    }
}

// ================================================ Phase 4: Viterbi + trace
__global__ void viterbi_kernel(const float* __restrict__ trans,
                               float* __restrict__ out, int out_size)
{
    __shared__ uint8_t bps[T_LEN][C_TAGS];   // 24 KB
    __shared__ float   fvs[2][16];           // double-buffered: 1 syncwarp/step

    const int lane = threadIdx.x;
    float tr[C_TAGS];
    if (lane < C_TAGS) {
        #pragma unroll
        for (int p = 0; p < C_TAGS; p++) tr[p] = trans[lane * C_TAGS + p];
    }
    float fv = (lane == START_TAG) ? 0.f : NEGV;

    auto featload = [&](int idx) -> float {
        return (lane < C_TAGS && idx < T_LEN) ? g_feats[idx][lane] : 0.f;
    };
    auto vstep = [&](int t, float ft) {
        const int cb = t & 1;
        if (lane < C_TAGS) fvs[cb][lane] = fv;
        __syncwarp();
        if (lane < C_TAGS) {
            float s[C_TAGS];
            #pragma unroll
            for (int p = 0; p < C_TAGS; p++) s[p] = fvs[cb][p] + tr[p];
            float m01 = fmaxf(s[0], s[1]),  m23 = fmaxf(s[2], s[3]);
            float m45 = fmaxf(s[4], s[5]),  m67 = fmaxf(s[6], s[7]);
            float m89 = fmaxf(s[8], s[9]),  mab = fmaxf(s[10], s[11]);
            float best = fmaxf(fmaxf(fmaxf(m01, m23), fmaxf(m45, m67)),
                               fmaxf(m89, mab));
            unsigned mask = 0;
            #pragma unroll
            for (int p = 0; p < C_TAGS; p++)
                mask |= (s[p] == best) ? (1u << p) : 0u;
            bps[t][lane] = (uint8_t)(__ffs(mask) - 1);
            fv = best + ft;
        }
    };

    float f0 = featload(0), f1 = featload(1), f2 = featload(2), f3 = featload(3);
    for (int t = 0; t < T_LEN; t += 4) {
        float n0 = featload(t + 4), n1 = featload(t + 5);
        float n2 = featload(t + 6), n3 = featload(t + 7);
        vstep(t + 0, f0);
        vstep(t + 1, f1);
        vstep(t + 2, f2);
        vstep(t + 3, f3);
        f0 = n0; f1 = n1; f2 = n2; f3 = n3;
    }

    if (lane < C_TAGS) fvs[0][lane] = fv + trans[STOP_TAG * C_TAGS + lane];
    __syncwarp();

    if (lane == 0) {
        float best = fvs[0][0]; int bt = 0;
        #pragma unroll
        for (int p = 1; p < C_TAGS; p++)
            if (fvs[0][p] > best) { best = fvs[0][p]; bt = p; }

        if (out_size >= 1) out[0] = best;
        if (out_size >= T_LEN + 1) {
            int tag = bt;
            for (int t = T_LEN - 1; t >= 1; t--) {
                out[1 + t] = (float)tag;
                tag = bps[t][tag];
            }
            out[1] = (float)tag;
        }
    }
}

// ================================================================= launch
extern "C" void kernel_launch(void* const* d_in, const int* in_sizes, int n_in,
                              void* d_out, int out_size)
{
    const int*   sent   = (const int*)  d_in[0];
    const float* emb    = (const float*)d_in[1];
    const float* Wih_f  = (const float*)d_in[2];
    const float* Whh_f  = (const float*)d_in[3];
    const float* bih_f  = (const float*)d_in[4];
    const float* bhh_f  = (const float*)d_in[5];
    const float* Wih_b  = (const float*)d_in[6];
    const float* Whh_b  = (const float*)d_in[7];
    const float* bih_b  = (const float*)d_in[8];
    const float* bhh_b  = (const float*)d_in[9];
    const float* Wlin   = (const float*)d_in[10];
    const float* blin   = (const float*)d_in[11];
    const float* h0     = (const float*)d_in[12];
    const float* c0     = (const float*)d_in[13];
    const float* transi = (const float*)d_in[14];
    float* out = (float*)d_out;

    // two dummy launches keep ncu's fixed capture slot on lstm_rec
    nop_kernel<<<1, 1>>>();
    nop_kernel<<<1, 1>>>();

    gates_gemm<<<dim3(T_LEN / 32, G4 / 32, 2), 256>>>(
        sent, emb, Wih_f, bih_f, bhh_f, Wih_b, bih_b, bhh_b);

    lstm_rec<<<16, 512>>>(Whh_f, Whh_b, h0, c0);

    feats_kernel<<<T_LEN / 8, 256>>>(Wlin, blin);

    viterbi_kernel<<<1, 32>>>(transi, out, out_size);
}

// round 13
// speedup vs baseline: 1.4711x; 1.4711x over previous
#include <cuda_runtime.h>
#include <cuda_bf16.h>
#include <cstdint>

#define T_LEN 2048
#define EMB   256
#define H2    256
#define G4    1024
#define C_TAGS 12
#define NEGV  (-10000.0f)
#define START_TAG 10
#define STOP_TAG  11

// padded h layout: 4 segments of 64 floats, stride 68 floats (272B)
// -> the 4 segment bases hit different banks (conflict-free LDS.128)
#define HPAD 272            // floats per h buffer (4*68)
#define HBUF_BYTES 1088     // HPAD * 4

// ---------------------------------------------------------------- scratch
__device__ float g_pre[2][T_LEN][G4];    // 16 MB: gate pre-activations
__device__ float g_hs[2][T_LEN][H2];     // 4 MB: hidden states per direction
__device__ float g_feats[T_LEN][C_TAGS]; // 96 KB

__device__ __forceinline__ uint32_t smem_u32(const void* p) {
    return (uint32_t)__cvta_generic_to_shared(p);
}

__device__ __forceinline__ float fast_sig(float x) {
    return __fdividef(1.0f, 1.0f + __expf(-x));
}
__device__ __forceinline__ float fast_tanh(float x) {
    return __fdividef(2.0f, 1.0f + __expf(-2.0f * x)) - 1.0f;
}

__device__ __forceinline__ void fma2(uint64_t& d, uint64_t a, uint64_t b) {
    asm("fma.rn.f32x2 %0, %1, %2, %0;" : "+l"(d) : "l"(a), "l"(b));
}
__device__ __forceinline__ float unpack_sum(uint64_t a) {
    float lo, hi;
    asm("mov.b64 {%0, %1}, %2;" : "=f"(lo), "=f"(hi) : "l"(a));
    return lo + hi;
}

// dummy kernel: shifts ncu's fixed capture slot onto lstm_rec
__global__ void nop_kernel() {}

// ============================================================ Phase 1: GEMM
__global__ void gates_gemm(const int* __restrict__ sent,
                           const float* __restrict__ emb,
                           const float* __restrict__ Wih_f,
                           const float* __restrict__ bih_f,
                           const float* __restrict__ bhh_f,
                           const float* __restrict__ Wih_b,
                           const float* __restrict__ bih_b,
                           const float* __restrict__ bhh_b)
{
    const int dir = blockIdx.z;
    const float* Wih = dir ? Wih_b : Wih_f;
    const float* bih = dir ? bih_b : bih_f;
    const float* bhh = dir ? bhh_b : bhh_f;
    const int t0 = blockIdx.x * 32;
    const int r0 = blockIdx.y * 32;
    const int tid = threadIdx.x;
    const int lane = tid & 31;
    const int warp = tid >> 5;

    __shared__ float Xs[32][33];
    __shared__ float Ws[32][33];
    __shared__ int   sidx[32];

    if (tid < 32) sidx[tid] = sent[t0 + tid];
    __syncthreads();

    float acc[4] = {0.f, 0.f, 0.f, 0.f};
    for (int kc = 0; kc < EMB; kc += 32) {
        #pragma unroll
        for (int e = 0; e < 4; e++) {
            int idx = tid + 256 * e;
            int a = idx >> 5, b = idx & 31;
            Xs[a][b] = emb[(long long)sidx[a] * EMB + kc + b];
            Ws[a][b] = Wih[(r0 + a) * EMB + kc + b];
        }
        __syncthreads();
        #pragma unroll
        for (int k = 0; k < 32; k++) {
            float wk = Ws[lane][k];
            #pragma unroll
            for (int e = 0; e < 4; e++)
                acc[e] += Xs[warp + 8 * e][k] * wk;
        }
        __syncthreads();
    }
    float bias = bih[r0 + lane] + bhh[r0 + lane];
    #pragma unroll
    for (int e = 0; e < 4; e++)
        g_pre[dir][t0 + warp + 8 * e][r0 + lane] = acc[e] + bias;
}

// ====================================================== Phase 2: recurrence
// Round-6 structure (best timed baseline): producers compute gate dots +
// nonlinearity -> gates[] smem, per-warp gbar arrive; updater warp 0 does
// the cell update and broadcasts h via plain st.shared::cluster.
// SINGLE CHANGE vs r6: the fence.acq_rel.cluster before the 8 remote
// arrives is REMOVED — arrives are issued after __syncwarp (so after all
// 32 lanes' remote stores are issued) and rely on per-link FIFO ordering
// of the DSMEM fabric. Consumer wait keeps acquire.cluster.
__global__ void __cluster_dims__(8, 1, 1) __launch_bounds__(512, 1)
lstm_rec(const float* __restrict__ Whh_f,
         const float* __restrict__ Whh_b,
         const float* __restrict__ h0,
         const float* __restrict__ c0)
{
    const int dir  = blockIdx.x >> 3;
    unsigned rank;
    asm("mov.u32 %0, %%cluster_ctarank;" : "=r"(rank));
    const float* Whh = dir ? Whh_b : Whh_f;

    const int tid = threadIdx.x;
    const int lr  = tid >> 2;     // local gate row 0..127
    const int seg = tid & 3;      // 64-col segment
    const int gg  = lr >> 5;      // gate id 0..3 (i,f,g,o)
    const int jj  = lr & 31;      // h index within CTA
    const int grow = (gg << 8) + (int)(rank << 5) + jj;

    __shared__ __align__(16) float hbuf[2][HPAD]; // hbuf[1] = hbuf[0]+1088B
    __shared__ float    gates[128];
    __shared__ uint64_t bars[2];                  // bars[1] = bars[0] + 8B
    __shared__ uint64_t gbar;

    // weights -> packed f32x2 registers
    uint64_t w2[32];
    {
        const ulonglong2* wp = (const ulonglong2*)(Whh + grow * H2 + seg * 64);
        #pragma unroll
        for (int i = 0; i < 16; i++) {
            ulonglong2 v = wp[i];
            w2[2*i] = v.x; w2[2*i+1] = v.y;
        }
    }

    // init h (padded layout), c, barriers
    if (tid < H2) hbuf[0][(tid >> 6) * 68 + (tid & 63)] = h0[dir * H2 + tid];
    float creg = 0.f;
    if (tid < 32) creg = c0[dir * H2 + (int)rank * 32 + tid];

    const uint32_t bar0 = smem_u32(&bars[0]);
    const uint32_t bar1 = smem_u32(&bars[1]);
    const uint32_t gb   = smem_u32(&gbar);
    if (tid == 0) {
        asm volatile("mbarrier.init.shared.b64 [%0], %1;" :: "r"(bar0), "r"(8) : "memory");
        asm volatile("mbarrier.init.shared.b64 [%0], %1;" :: "r"(bar1), "r"(8) : "memory");
        asm volatile("mbarrier.init.shared.b64 [%0], %1;" :: "r"(gb),   "r"(16) : "memory");
    }
    __syncthreads();
    asm volatile("barrier.cluster.arrive.aligned;" ::: "memory");
    asm volatile("barrier.cluster.wait.aligned;"  ::: "memory");

    // updater remote addressing: base + r*stride (2 regs, not 8)
    uint32_t ha_base = 0, ha_step = 0, rb = 0;
    if (tid < 32) {
        const int hidx = (int)rank * 32 + tid;
        uint32_t loc0 = smem_u32(&hbuf[0][(hidx >> 6) * 68 + (hidx & 63)]);
        uint32_t a0, a1;
        asm("mapa.shared::cluster.u32 %0, %1, %2;" : "=r"(a0) : "r"(loc0), "r"(0));
        asm("mapa.shared::cluster.u32 %0, %1, %2;" : "=r"(a1) : "r"(loc0), "r"(1));
        ha_base = a0; ha_step = a1 - a0;
        if (tid < 8)
            asm("mapa.shared::cluster.u32 %0, %1, %2;" : "=r"(rb) : "r"(bar0), "r"(tid));
    }

    int ph0 = 0, ph1 = 0, gph = 0;

    // pre-load step-0 pre-activation
    float gp = 0.f;
    if (seg == 0) gp = g_pre[dir][dir ? (T_LEN - 1) : 0][grow];

    for (int it = 0; it < T_LEN; it++) {
        const int buf = it & 1;
        const int t = dir ? (T_LEN - 1 - it) : it;

        if (it > 0) {
            uint32_t ba = buf ? bar1 : bar0;
            int      ph = buf ? ph1  : ph0;
            asm volatile(
                "{\n\t.reg .pred P;\n\t"
                "BW_%=:\n\t"
                "mbarrier.try_wait.parity.acquire.cluster.shared::cta.b64 P, [%0], %1, 0x989680;\n\t"
                "@P bra.uni BWD_%=;\n\t"
                "bra.uni BW_%=;\n\t"
                "BWD_%=:\n\t}"
                :: "r"(ba), "r"(ph) : "memory");
            if (buf) ph1 ^= 1; else ph0 ^= 1;
        }

        // prefetch NEXT step's pre-activation (hidden behind this step)
        float gpn = 0.f;
        if (seg == 0 && it + 1 < T_LEN) {
            int tn = dir ? (T_LEN - 2 - it) : (it + 1);
            gpn = g_pre[dir][tn][grow];
        }

        // h . w on packed f32x2 (4 accumulator chains, conflict-free LDS)
        const ulonglong2* hp2 = (const ulonglong2*)(hbuf[buf] + seg * 68);
        uint64_t a0 = 0, a1 = 0, a2 = 0, a3 = 0;
        #pragma unroll
        for (int i = 0; i < 8; i++) {
            ulonglong2 hva = hp2[2*i];
            ulonglong2 hvb = hp2[2*i + 1];
            fma2(a0, w2[4*i],     hva.x);
            fma2(a1, w2[4*i + 1], hva.y);
            fma2(a2, w2[4*i + 2], hvb.x);
            fma2(a3, w2[4*i + 3], hvb.y);
        }
        float acc = (unpack_sum(a0) + unpack_sum(a1)) +
                    (unpack_sum(a2) + unpack_sum(a3));
        acc += __shfl_down_sync(0xffffffffu, acc, 2, 4);
        acc += __shfl_down_sync(0xffffffffu, acc, 1, 4);
        if (seg == 0) {
            float raw = acc + gp;
            gates[lr] = (gg == 2) ? fast_tanh(raw) : fast_sig(raw);
        }
        __syncwarp();
        if ((tid & 31) == 0)
            asm volatile("mbarrier.arrive.shared.b64 _, [%0];" :: "r"(gb) : "memory");
        gp = gpn;

        if (tid < 32) {
            asm volatile(
                "{\n\t.reg .pred P;\n\t"
                "GW_%=:\n\t"
                "mbarrier.try_wait.parity.acquire.cta.shared::cta.b64 P, [%0], %1, 0x989680;\n\t"
                "@P bra.uni GWD_%=;\n\t"
                "bra.uni GW_%=;\n\t"
                "GWD_%=:\n\t}"
                :: "r"(gb), "r"(gph) : "memory");
            gph ^= 1;

            float I = gates[tid];
            float F = gates[32 + tid];
            float G = gates[64 + tid];
            float O = gates[96 + tid];
            creg = F * creg + I * G;
            float h = O * fast_tanh(creg);

            if (it < T_LEN - 1) {
                const uint32_t boff = (buf ^ 1) ? (uint32_t)HBUF_BYTES : 0u;  // next buffer
                uint32_t addr = ha_base + boff;
                #pragma unroll
                for (int r = 0; r < 8; r++) {
                    asm volatile("st.shared::cluster.f32 [%0], %1;"
                                 :: "r"(addr), "f"(h) : "memory");
                    addr += ha_step;
                }
                __syncwarp();
                if (tid < 8) {
                    // NO fence: arrives issued after all lanes' stores;
                    // per-link FIFO ordering of the DSMEM fabric keeps
                    // each target's arrive behind that target's stores.
                    uint32_t ba = rb + ((buf ^ 1) ? 8u : 0u);
                    asm volatile(
                        "mbarrier.arrive.relaxed.cluster.shared::cluster.b64 _, [%0];"
                        :: "r"(ba) : "memory");
                }
            }
            g_hs[dir][t][(int)rank * 32 + tid] = h;
        }
    }
}

// ========================================================= Phase 3: feats
__global__ void feats_kernel(const float* __restrict__ Wlin,
                             const float* __restrict__ blin)
{
    __shared__ float Wl[C_TAGS][512];
    const int tid = threadIdx.x;
    for (int i = tid; i < C_TAGS * 512; i += 256)
        Wl[i >> 9][i & 511] = Wlin[i];
    __syncthreads();

    const int warp = tid >> 5, lane = tid & 31;
    const int t = blockIdx.x * 8 + warp;

    float hv[16];
    #pragma unroll
    for (int i = 0; i < 8; i++) hv[i]     = g_hs[0][t][lane + 32 * i];
    #pragma unroll
    for (int i = 0; i < 8; i++) hv[8 + i] = g_hs[1][t][lane + 32 * i];

    #pragma unroll
    for (int c = 0; c < C_TAGS; c++) {
        float a = 0.f;
        #pragma unroll
        for (int i = 0; i < 16; i++)
            a += hv[i] * Wl[c][lane + 32 * i];
        #pragma unroll
        for (int o = 16; o; o >>= 1)
            a += __shfl_down_sync(0xffffffffu, a, o);
        if (lane == 0) g_feats[t][c] = a + blin[c];
    }
}

// ================================================ Phase 4: Viterbi + trace
__global__ void viterbi_kernel(const float* __restrict__ trans,
                               float* __restrict__ out, int out_size)
{
    __shared__ uint8_t bps[T_LEN][C_TAGS];   // 24 KB
    __shared__ float   fvs[2][16];           // double-buffered: 1 syncwarp/step

    const int lane = threadIdx.x;
    float tr[C_TAGS];
    if (lane < C_TAGS) {
        #pragma unroll
        for (int p = 0; p < C_TAGS; p++) tr[p] = trans[lane * C_TAGS + p];
    }
    float fv = (lane == START_TAG) ? 0.f : NEGV;

    auto featload = [&](int idx) -> float {
        return (lane < C_TAGS && idx < T_LEN) ? g_feats[idx][lane] : 0.f;
    };
    auto vstep = [&](int t, float ft) {
        const int cb = t & 1;
        if (lane < C_TAGS) fvs[cb][lane] = fv;
        __syncwarp();
        if (lane < C_TAGS) {
            float s[C_TAGS];
            #pragma unroll
            for (int p = 0; p < C_TAGS; p++) s[p] = fvs[cb][p] + tr[p];
            float m01 = fmaxf(s[0], s[1]),  m23 = fmaxf(s[2], s[3]);
            float m45 = fmaxf(s[4], s[5]),  m67 = fmaxf(s[6], s[7]);
            float m89 = fmaxf(s[8], s[9]),  mab = fmaxf(s[10], s[11]);
            float best = fmaxf(fmaxf(fmaxf(m01, m23), fmaxf(m45, m67)),
                               fmaxf(m89, mab));
            unsigned mask = 0;
            #pragma unroll
            for (int p = 0; p < C_TAGS; p++)
                mask |= (s[p] == best) ? (1u << p) : 0u;
            bps[t][lane] = (uint8_t)(__ffs(mask) - 1);
            fv = best + ft;
        }
    };

    float f0 = featload(0), f1 = featload(1), f2 = featload(2), f3 = featload(3);
    for (int t = 0; t < T_LEN; t += 4) {
        float n0 = featload(t + 4), n1 = featload(t + 5);
        float n2 = featload(t + 6), n3 = featload(t + 7);
        vstep(t + 0, f0);
        vstep(t + 1, f1);
        vstep(t + 2, f2);
        vstep(t + 3, f3);
        f0 = n0; f1 = n1; f2 = n2; f3 = n3;
    }

    if (lane < C_TAGS) fvs[0][lane] = fv + trans[STOP_TAG * C_TAGS + lane];
    __syncwarp();

    if (lane == 0) {
        float best = fvs[0][0]; int bt = 0;
        #pragma unroll
        for (int p = 1; p < C_TAGS; p++)
            if (fvs[0][p] > best) { best = fvs[0][p]; bt = p; }

        if (out_size >= 1) out[0] = best;
        if (out_size >= T_LEN + 1) {
            int tag = bt;
            for (int t = T_LEN - 1; t >= 1; t--) {
                out[1 + t] = (float)tag;
                tag = bps[t][tag];
            }
            out[1] = (float)tag;
        }
    }
}

// ================================================================= launch
extern "C" void kernel_launch(void* const* d_in, const int* in_sizes, int n_in,
                              void* d_out, int out_size)
{
    const int*   sent   = (const int*)  d_in[0];
    const float* emb    = (const float*)d_in[1];
    const float* Wih_f  = (const float*)d_in[2];
    const float* Whh_f  = (const float*)d_in[3];
    const float* bih_f  = (const float*)d_in[4];
    const float* bhh_f  = (const float*)d_in[5];
    const float* Wih_b  = (const float*)d_in[6];
    const float* Whh_b  = (const float*)d_in[7];
    const float* bih_b  = (const float*)d_in[8];
    const float* bhh_b  = (const float*)d_in[9];
    const float* Wlin   = (const float*)d_in[10];
    const float* blin   = (const float*)d_in[11];
    const float* h0     = (const float*)d_in[12];
    const float* c0     = (const float*)d_in[13];
    const float* transi = (const float*)d_in[14];
    float* out = (float*)d_out;

    // two dummy launches keep ncu's fixed capture slot on lstm_rec
    nop_kernel<<<1, 1>>>();
    nop_kernel<<<1, 1>>>();

    gates_gemm<<<dim3(T_LEN / 32, G4 / 32, 2), 256>>>(
        sent, emb, Wih_f, bih_f, bhh_f, Wih_b, bih_b, bhh_b);

    lstm_rec<<<16, 512>>>(Whh_f, Whh_b, h0, c0);

    feats_kernel<<<T_LEN / 8, 256>>>(Wlin, blin);

    viterbi_kernel<<<1, 32>>>(transi, out, out_size);
}

// round 14
// speedup vs baseline: 1.6687x; 1.1343x over previous
#include <cuda_runtime.h>
#include <cuda_bf16.h>
#include <cstdint>

#define T_LEN 2048
#define EMB   256
#define H2    256
#define G4    1024
#define C_TAGS 12
#define NEGV  (-10000.0f)
#define START_TAG 10
#define STOP_TAG  11

// padded h layout: 4 segments of 64 floats, stride 68 floats (272B)
// -> the 4 segment bases hit different banks (conflict-free LDS.128)
#define HPAD 272            // floats per h buffer (4*68)
#define HBUF_BYTES 1088     // HPAD * 4

// ---------------------------------------------------------------- scratch
__device__ float g_pre[2][T_LEN][G4];    // 16 MB: gate pre-activations
__device__ float g_hs[2][T_LEN][H2];     // 4 MB: hidden states per direction
__device__ float g_feats[T_LEN][C_TAGS]; // 96 KB

__device__ __forceinline__ uint32_t smem_u32(const void* p) {
    return (uint32_t)__cvta_generic_to_shared(p);
}

__device__ __forceinline__ float fast_sig(float x) {
    return __fdividef(1.0f, 1.0f + __expf(-x));
}
__device__ __forceinline__ float fast_tanh(float x) {
    return __fdividef(2.0f, 1.0f + __expf(-2.0f * x)) - 1.0f;
}

__device__ __forceinline__ void fma2(uint64_t& d, uint64_t a, uint64_t b) {
    asm("fma.rn.f32x2 %0, %1, %2, %0;" : "+l"(d) : "l"(a), "l"(b));
}
__device__ __forceinline__ float unpack_sum(uint64_t a) {
    float lo, hi;
    asm("mov.b64 {%0, %1}, %2;" : "=f"(lo), "=f"(hi) : "l"(a));
    return lo + hi;
}

// dummy kernel: shifts ncu's fixed capture slot onto lstm_rec
__global__ void nop_kernel() {}

// ============================================================ Phase 1: GEMM
__global__ void gates_gemm(const int* __restrict__ sent,
                           const float* __restrict__ emb,
                           const float* __restrict__ Wih_f,
                           const float* __restrict__ bih_f,
                           const float* __restrict__ bhh_f,
                           const float* __restrict__ Wih_b,
                           const float* __restrict__ bih_b,
                           const float* __restrict__ bhh_b)
{
    const int dir = blockIdx.z;
    const float* Wih = dir ? Wih_b : Wih_f;
    const float* bih = dir ? bih_b : bih_f;
    const float* bhh = dir ? bhh_b : bhh_f;
    const int t0 = blockIdx.x * 32;
    const int r0 = blockIdx.y * 32;
    const int tid = threadIdx.x;
    const int lane = tid & 31;
    const int warp = tid >> 5;

    __shared__ float Xs[32][33];
    __shared__ float Ws[32][33];
    __shared__ int   sidx[32];

    if (tid < 32) sidx[tid] = sent[t0 + tid];
    __syncthreads();

    float acc[4] = {0.f, 0.f, 0.f, 0.f};
    for (int kc = 0; kc < EMB; kc += 32) {
        #pragma unroll
        for (int e = 0; e < 4; e++) {
            int idx = tid + 256 * e;
            int a = idx >> 5, b = idx & 31;
            Xs[a][b] = emb[(long long)sidx[a] * EMB + kc + b];
            Ws[a][b] = Wih[(r0 + a) * EMB + kc + b];
        }
        __syncthreads();
        #pragma unroll
        for (int k = 0; k < 32; k++) {
            float wk = Ws[lane][k];
            #pragma unroll
            for (int e = 0; e < 4; e++)
                acc[e] += Xs[warp + 8 * e][k] * wk;
        }
        __syncthreads();
    }
    float bias = bih[r0 + lane] + bhh[r0 + lane];
    #pragma unroll
    for (int e = 0; e < 4; e++)
        g_pre[dir][t0 + warp + 8 * e][r0 + lane] = acc[e] + bias;
}

// ====================================================== Phase 2: recurrence
// Round-13 winner + two hop reductions:
//  (1) gates hop: mbarrier gbar -> named barrier (bar.arrive from warps
//      1..15, bar.sync from updater warp 0; ~47cyc effective, drains STS)
//  (2) step-barrier wait scope: acquire.cluster -> acquire.cta (data lands
//      in our physical smem; cta-scope acquire stops local reordering —
//      correctness already validated in round 9's protocol)
// Producer->consumer remote path stays fence-free (r13-proven FIFO).
__global__ void __cluster_dims__(8, 1, 1) __launch_bounds__(512, 1)
lstm_rec(const float* __restrict__ Whh_f,
         const float* __restrict__ Whh_b,
         const float* __restrict__ h0,
         const float* __restrict__ c0)
{
    const int dir  = blockIdx.x >> 3;
    unsigned rank;
    asm("mov.u32 %0, %%cluster_ctarank;" : "=r"(rank));
    const float* Whh = dir ? Whh_b : Whh_f;

    const int tid = threadIdx.x;
    const int lr  = tid >> 2;     // local gate row 0..127
    const int seg = tid & 3;      // 64-col segment
    const int gg  = lr >> 5;      // gate id 0..3 (i,f,g,o)
    const int jj  = lr & 31;      // h index within CTA
    const int grow = (gg << 8) + (int)(rank << 5) + jj;

    __shared__ __align__(16) float hbuf[2][HPAD]; // hbuf[1] = hbuf[0]+1088B
    __shared__ float    gates[128];
    __shared__ uint64_t bars[2];                  // bars[1] = bars[0] + 8B

    // weights -> packed f32x2 registers
    uint64_t w2[32];
    {
        const ulonglong2* wp = (const ulonglong2*)(Whh + grow * H2 + seg * 64);
        #pragma unroll
        for (int i = 0; i < 16; i++) {
            ulonglong2 v = wp[i];
            w2[2*i] = v.x; w2[2*i+1] = v.y;
        }
    }

    // init h (padded layout), c, barriers
    if (tid < H2) hbuf[0][(tid >> 6) * 68 + (tid & 63)] = h0[dir * H2 + tid];
    float creg = 0.f;
    if (tid < 32) creg = c0[dir * H2 + (int)rank * 32 + tid];

    const uint32_t bar0 = smem_u32(&bars[0]);
    const uint32_t bar1 = smem_u32(&bars[1]);
    if (tid == 0) {
        asm volatile("mbarrier.init.shared.b64 [%0], %1;" :: "r"(bar0), "r"(8) : "memory");
        asm volatile("mbarrier.init.shared.b64 [%0], %1;" :: "r"(bar1), "r"(8) : "memory");
    }
    __syncthreads();
    asm volatile("barrier.cluster.arrive.aligned;" ::: "memory");
    asm volatile("barrier.cluster.wait.aligned;"  ::: "memory");

    // updater remote addressing: base + r*stride (2 regs, not 8)
    uint32_t ha_base = 0, ha_step = 0, rb = 0;
    if (tid < 32) {
        const int hidx = (int)rank * 32 + tid;
        uint32_t loc0 = smem_u32(&hbuf[0][(hidx >> 6) * 68 + (hidx & 63)]);
        uint32_t a0, a1;
        asm("mapa.shared::cluster.u32 %0, %1, %2;" : "=r"(a0) : "r"(loc0), "r"(0));
        asm("mapa.shared::cluster.u32 %0, %1, %2;" : "=r"(a1) : "r"(loc0), "r"(1));
        ha_base = a0; ha_step = a1 - a0;
        if (tid < 8)
            asm("mapa.shared::cluster.u32 %0, %1, %2;" : "=r"(rb) : "r"(bar0), "r"(tid));
    }

    int ph0 = 0, ph1 = 0;

    // pre-load step-0 pre-activation
    float gp = 0.f;
    if (seg == 0) gp = g_pre[dir][dir ? (T_LEN - 1) : 0][grow];

    for (int it = 0; it < T_LEN; it++) {
        const int buf = it & 1;
        const int t = dir ? (T_LEN - 1 - it) : it;

        if (it > 0) {
            uint32_t ba = buf ? bar1 : bar0;
            int      ph = buf ? ph1  : ph0;
            asm volatile(
                "{\n\t.reg .pred P;\n\t"
                "BW_%=:\n\t"
                "mbarrier.try_wait.parity.acquire.cta.shared::cta.b64 P, [%0], %1, 0x989680;\n\t"
                "@P bra.uni BWD_%=;\n\t"
                "bra.uni BW_%=;\n\t"
                "BWD_%=:\n\t}"
                :: "r"(ba), "r"(ph) : "memory");
            if (buf) ph1 ^= 1; else ph0 ^= 1;
        }

        // prefetch NEXT step's pre-activation (hidden behind this step)
        float gpn = 0.f;
        if (seg == 0 && it + 1 < T_LEN) {
            int tn = dir ? (T_LEN - 2 - it) : (it + 1);
            gpn = g_pre[dir][tn][grow];
        }

        // h . w on packed f32x2 (4 accumulator chains, conflict-free LDS)
        const ulonglong2* hp2 = (const ulonglong2*)(hbuf[buf] + seg * 68);
        uint64_t a0 = 0, a1 = 0, a2 = 0, a3 = 0;
        #pragma unroll
        for (int i = 0; i < 8; i++) {
            ulonglong2 hva = hp2[2*i];
            ulonglong2 hvb = hp2[2*i + 1];
            fma2(a0, w2[4*i],     hva.x);
            fma2(a1, w2[4*i + 1], hva.y);
            fma2(a2, w2[4*i + 2], hvb.x);
            fma2(a3, w2[4*i + 3], hvb.y);
        }
        float acc = (unpack_sum(a0) + unpack_sum(a1)) +
                    (unpack_sum(a2) + unpack_sum(a3));
        acc += __shfl_down_sync(0xffffffffu, acc, 2, 4);
        acc += __shfl_down_sync(0xffffffffu, acc, 1, 4);
        if (seg == 0) {
            float raw = acc + gp;
            gates[lr] = (gg == 2) ? fast_tanh(raw) : fast_sig(raw);
        }
        gp = gpn;

        // gates handoff: named barrier 1, 512 threads total.
        // Warps 1..15 arrive (non-blocking); updater warp 0 syncs.
        // bar drains the STS above, so gates[] is visible to warp 0.
        if (tid >= 32) {
            asm volatile("bar.arrive 1, 512;" ::: "memory");
        } else {
            asm volatile("bar.sync 1, 512;" ::: "memory");

            float I = gates[tid];
            float F = gates[32 + tid];
            float G = gates[64 + tid];
            float O = gates[96 + tid];
            creg = F * creg + I * G;
            float h = O * fast_tanh(creg);

            if (it < T_LEN - 1) {
                const uint32_t boff = (buf ^ 1) ? (uint32_t)HBUF_BYTES : 0u;  // next buffer
                uint32_t addr = ha_base + boff;
                #pragma unroll
                for (int r = 0; r < 8; r++) {
                    asm volatile("st.shared::cluster.f32 [%0], %1;"
                                 :: "r"(addr), "f"(h) : "memory");
                    addr += ha_step;
                }
                __syncwarp();
                if (tid < 8) {
                    // NO fence: arrives issued after all lanes' stores;
                    // per-link FIFO ordering of the DSMEM fabric keeps
                    // each target's arrive behind that target's stores
                    // (empirically validated in round 13).
                    uint32_t ba = rb + ((buf ^ 1) ? 8u : 0u);
                    asm volatile(
                        "mbarrier.arrive.relaxed.cluster.shared::cluster.b64 _, [%0];"
                        :: "r"(ba) : "memory");
                }
            }
            g_hs[dir][t][(int)rank * 32 + tid] = h;
        }
    }
}

// ========================================================= Phase 3: feats
__global__ void feats_kernel(const float* __restrict__ Wlin,
                             const float* __restrict__ blin)
{
    __shared__ float Wl[C_TAGS][512];
    const int tid = threadIdx.x;
    for (int i = tid; i < C_TAGS * 512; i += 256)
        Wl[i >> 9][i & 511] = Wlin[i];
    __syncthreads();

    const int warp = tid >> 5, lane = tid & 31;
    const int t = blockIdx.x * 8 + warp;

    float hv[16];
    #pragma unroll
    for (int i = 0; i < 8; i++) hv[i]     = g_hs[0][t][lane + 32 * i];
    #pragma unroll
    for (int i = 0; i < 8; i++) hv[8 + i] = g_hs[1][t][lane + 32 * i];

    #pragma unroll
    for (int c = 0; c < C_TAGS; c++) {
        float a = 0.f;
        #pragma unroll
        for (int i = 0; i < 16; i++)
            a += hv[i] * Wl[c][lane + 32 * i];
        #pragma unroll
        for (int o = 16; o; o >>= 1)
            a += __shfl_down_sync(0xffffffffu, a, o);
        if (lane == 0) g_feats[t][c] = a + blin[c];
    }
}

// ================================================ Phase 4: Viterbi + trace
__global__ void viterbi_kernel(const float* __restrict__ trans,
                               float* __restrict__ out, int out_size)
{
    __shared__ uint8_t bps[T_LEN][C_TAGS];   // 24 KB
    __shared__ float   fvs[2][16];           // double-buffered: 1 syncwarp/step

    const int lane = threadIdx.x;
    float tr[C_TAGS];
    if (lane < C_TAGS) {
        #pragma unroll
        for (int p = 0; p < C_TAGS; p++) tr[p] = trans[lane * C_TAGS + p];
    }
    float fv = (lane == START_TAG) ? 0.f : NEGV;

    auto featload = [&](int idx) -> float {
        return (lane < C_TAGS && idx < T_LEN) ? g_feats[idx][lane] : 0.f;
    };
    auto vstep = [&](int t, float ft) {
        const int cb = t & 1;
        if (lane < C_TAGS) fvs[cb][lane] = fv;
        __syncwarp();
        if (lane < C_TAGS) {
            float s[C_TAGS];
            #pragma unroll
            for (int p = 0; p < C_TAGS; p++) s[p] = fvs[cb][p] + tr[p];
            float m01 = fmaxf(s[0], s[1]),  m23 = fmaxf(s[2], s[3]);
            float m45 = fmaxf(s[4], s[5]),  m67 = fmaxf(s[6], s[7]);
            float m89 = fmaxf(s[8], s[9]),  mab = fmaxf(s[10], s[11]);
            float best = fmaxf(fmaxf(fmaxf(m01, m23), fmaxf(m45, m67)),
                               fmaxf(m89, mab));
            unsigned mask = 0;
            #pragma unroll
            for (int p = 0; p < C_TAGS; p++)
                mask |= (s[p] == best) ? (1u << p) : 0u;
            bps[t][lane] = (uint8_t)(__ffs(mask) - 1);
            fv = best + ft;
        }
    };

    float f0 = featload(0), f1 = featload(1), f2 = featload(2), f3 = featload(3);
    for (int t = 0; t < T_LEN; t += 4) {
        float n0 = featload(t + 4), n1 = featload(t + 5);
        float n2 = featload(t + 6), n3 = featload(t + 7);
        vstep(t + 0, f0);
        vstep(t + 1, f1);
        vstep(t + 2, f2);
        vstep(t + 3, f3);
        f0 = n0; f1 = n1; f2 = n2; f3 = n3;
    }

    if (lane < C_TAGS) fvs[0][lane] = fv + trans[STOP_TAG * C_TAGS + lane];
    __syncwarp();

    if (lane == 0) {
        float best = fvs[0][0]; int bt = 0;
        #pragma unroll
        for (int p = 1; p < C_TAGS; p++)
            if (fvs[0][p] > best) { best = fvs[0][p]; bt = p; }

        if (out_size >= 1) out[0] = best;
        if (out_size >= T_LEN + 1) {
            int tag = bt;
            for (int t = T_LEN - 1; t >= 1; t--) {
                out[1 + t] = (float)tag;
                tag = bps[t][tag];
            }
            out[1] = (float)tag;
        }
    }
}

// ================================================================= launch
extern "C" void kernel_launch(void* const* d_in, const int* in_sizes, int n_in,
                              void* d_out, int out_size)
{
    const int*   sent   = (const int*)  d_in[0];
    const float* emb    = (const float*)d_in[1];
    const float* Wih_f  = (const float*)d_in[2];
    const float* Whh_f  = (const float*)d_in[3];
    const float* bih_f  = (const float*)d_in[4];
    const float* bhh_f  = (const float*)d_in[5];
    const float* Wih_b  = (const float*)d_in[6];
    const float* Whh_b  = (const float*)d_in[7];
    const float* bih_b  = (const float*)d_in[8];
    const float* bhh_b  = (const float*)d_in[9];
    const float* Wlin   = (const float*)d_in[10];
    const float* blin   = (const float*)d_in[11];
    const float* h0     = (const float*)d_in[12];
    const float* c0     = (const float*)d_in[13];
    const float* transi = (const float*)d_in[14];
    float* out = (float*)d_out;

    // two dummy launches keep ncu's fixed capture slot on lstm_rec
    nop_kernel<<<1, 1>>>();
    nop_kernel<<<1, 1>>>();

    gates_gemm<<<dim3(T_LEN / 32, G4 / 32, 2), 256>>>(
        sent, emb, Wih_f, bih_f, bhh_f, Wih_b, bih_b, bhh_b);

    lstm_rec<<<16, 512>>>(Whh_f, Whh_b, h0, c0);

    feats_kernel<<<T_LEN / 8, 256>>>(Wlin, blin);

    viterbi_kernel<<<1, 32>>>(transi, out, out_size);
}

// round 16
// speedup vs baseline: 1.7454x; 1.0460x over previous
#include <cuda_runtime.h>
#include <cuda_bf16.h>
#include <cstdint>

#define T_LEN 2048
#define EMB   256
#define H2    256
#define G4    1024
#define C_TAGS 12
#define NEGV  (-10000.0f)
#define START_TAG 10
#define STOP_TAG  11

// padded h layout: 4 segments of 64 floats, stride 68 floats (272B)
// -> the 4 segment bases hit different banks (conflict-free LDS.128)
#define HPAD 272            // floats per h buffer (4*68)
#define HBUF_BYTES 1088     // HPAD * 4

// ---------------------------------------------------------------- scratch
__device__ float g_pre[2][T_LEN][G4];    // 16 MB: gate pre-activations
__device__ float g_hs[2][T_LEN][H2];     // 4 MB: hidden states per direction
__device__ float g_feats[T_LEN][C_TAGS]; // 96 KB

__device__ __forceinline__ uint32_t smem_u32(const void* p) {
    return (uint32_t)__cvta_generic_to_shared(p);
}

// HW tanh (sm_75+): single MUFU op (~16 cyc vs ~40-56 for exp/div chains)
__device__ __forceinline__ float hw_tanh(float x) {
    float r;
    asm("tanh.approx.f32 %0, %1;" : "=f"(r) : "f"(x));
    return r;
}
__device__ __forceinline__ float hw_sig(float x) {
    // sigmoid(x) = 0.5 * tanh(0.5x) + 0.5  (MUL + MUFU + FMA)
    return fmaf(0.5f, hw_tanh(0.5f * x), 0.5f);
}

__device__ __forceinline__ void fma2(uint64_t& d, uint64_t a, uint64_t b) {
    asm("fma.rn.f32x2 %0, %1, %2, %0;" : "+l"(d) : "l"(a), "l"(b));
}
__device__ __forceinline__ float unpack_sum(uint64_t a) {
    float lo, hi;
    asm("mov.b64 {%0, %1}, %2;" : "=f"(lo), "=f"(hi) : "l"(a));
    return lo + hi;
}

// dummy kernel: shifts ncu's fixed capture slot onto lstm_rec
__global__ void nop_kernel() {}

// ============================================================ Phase 1: GEMM
__global__ void gates_gemm(const int* __restrict__ sent,
                           const float* __restrict__ emb,
                           const float* __restrict__ Wih_f,
                           const float* __restrict__ bih_f,
                           const float* __restrict__ bhh_f,
                           const float* __restrict__ Wih_b,
                           const float* __restrict__ bih_b,
                           const float* __restrict__ bhh_b)
{
    const int dir = blockIdx.z;
    const float* Wih = dir ? Wih_b : Wih_f;
    const float* bih = dir ? bih_b : bih_f;
    const float* bhh = dir ? bhh_b : bhh_f;
    const int t0 = blockIdx.x * 32;
    const int r0 = blockIdx.y * 32;
    const int tid = threadIdx.x;
    const int lane = tid & 31;
    const int warp = tid >> 5;

    __shared__ float Xs[32][33];
    __shared__ float Ws[32][33];
    __shared__ int   sidx[32];

    if (tid < 32) sidx[tid] = sent[t0 + tid];
    __syncthreads();

    float acc[4] = {0.f, 0.f, 0.f, 0.f};
    for (int kc = 0; kc < EMB; kc += 32) {
        #pragma unroll
        for (int e = 0; e < 4; e++) {
            int idx = tid + 256 * e;
            int a = idx >> 5, b = idx & 31;
            Xs[a][b] = emb[(long long)sidx[a] * EMB + kc + b];
            Ws[a][b] = Wih[(r0 + a) * EMB + kc + b];
        }
        __syncthreads();
        #pragma unroll
        for (int k = 0; k < 32; k++) {
            float wk = Ws[lane][k];
            #pragma unroll
            for (int e = 0; e < 4; e++)
                acc[e] += Xs[warp + 8 * e][k] * wk;
        }
        __syncthreads();
    }
    float bias = bih[r0 + lane] + bhh[r0 + lane];
    #pragma unroll
    for (int e = 0; e < 4; e++)
        g_pre[dir][t0 + warp + 8 * e][r0 + lane] = acc[e] + bias;
}

// ====================================================== Phase 2: recurrence
// Round-14 winner (verified 2666us), unchanged protocol:
//  - producers: dot + nonlinearity -> gates[] smem, named-bar arrive
//  - updater warp 0: named-bar sync, cell update, plain st.shared::cluster
//    broadcast, NO fence, 8 relaxed remote mbarrier arrives (r13-validated
//    fabric ordering: stores-then-ARRIVE stay ordered; plain data stamps
//    do NOT - r15 disproved that)
//  - step-barrier waits: mbarrier try_wait acquire.cta
// ONLY change vs r14: all nonlinearities use HW tanh.approx (MUFU).
__global__ void __cluster_dims__(8, 1, 1) __launch_bounds__(512, 1)
lstm_rec(const float* __restrict__ Whh_f,
         const float* __restrict__ Whh_b,
         const float* __restrict__ h0,
         const float* __restrict__ c0)
{
    const int dir  = blockIdx.x >> 3;
    unsigned rank;
    asm("mov.u32 %0, %%cluster_ctarank;" : "=r"(rank));
    const float* Whh = dir ? Whh_b : Whh_f;

    const int tid = threadIdx.x;
    const int lr  = tid >> 2;     // local gate row 0..127
    const int seg = tid & 3;      // 64-col segment
    const int gg  = lr >> 5;      // gate id 0..3 (i,f,g,o)
    const int jj  = lr & 31;      // h index within CTA
    const int grow = (gg << 8) + (int)(rank << 5) + jj;

    __shared__ __align__(16) float hbuf[2][HPAD]; // hbuf[1] = hbuf[0]+1088B
    __shared__ float    gates[128];
    __shared__ uint64_t bars[2];                  // bars[1] = bars[0] + 8B

    // weights -> packed f32x2 registers
    uint64_t w2[32];
    {
        const ulonglong2* wp = (const ulonglong2*)(Whh + grow * H2 + seg * 64);
        #pragma unroll
        for (int i = 0; i < 16; i++) {
            ulonglong2 v = wp[i];
            w2[2*i] = v.x; w2[2*i+1] = v.y;
        }
    }

    // init h (padded layout), c, barriers
    if (tid < H2) hbuf[0][(tid >> 6) * 68 + (tid & 63)] = h0[dir * H2 + tid];
    float creg = 0.f;
    if (tid < 32) creg = c0[dir * H2 + (int)rank * 32 + tid];

    const uint32_t bar0 = smem_u32(&bars[0]);
    const uint32_t bar1 = smem_u32(&bars[1]);
    if (tid == 0) {
        asm volatile("mbarrier.init.shared.b64 [%0], %1;" :: "r"(bar0), "r"(8) : "memory");
        asm volatile("mbarrier.init.shared.b64 [%0], %1;" :: "r"(bar1), "r"(8) : "memory");
    }
    __syncthreads();
    asm volatile("barrier.cluster.arrive.aligned;" ::: "memory");
    asm volatile("barrier.cluster.wait.aligned;"  ::: "memory");

    // updater remote addressing: base + r*stride (2 regs, not 8)
    uint32_t ha_base = 0, ha_step = 0, rb = 0;
    if (tid < 32) {
        const int hidx = (int)rank * 32 + tid;
        uint32_t loc0 = smem_u32(&hbuf[0][(hidx >> 6) * 68 + (hidx & 63)]);
        uint32_t a0, a1;
        asm("mapa.shared::cluster.u32 %0, %1, %2;" : "=r"(a0) : "r"(loc0), "r"(0));
        asm("mapa.shared::cluster.u32 %0, %1, %2;" : "=r"(a1) : "r"(loc0), "r"(1));
        ha_base = a0; ha_step = a1 - a0;
        if (tid < 8)
            asm("mapa.shared::cluster.u32 %0, %1, %2;" : "=r"(rb) : "r"(bar0), "r"(tid));
    }

    int ph0 = 0, ph1 = 0;

    // pre-load step-0 pre-activation
    float gp = 0.f;
    if (seg == 0) gp = g_pre[dir][dir ? (T_LEN - 1) : 0][grow];

    for (int it = 0; it < T_LEN; it++) {
        const int buf = it & 1;
        const int t = dir ? (T_LEN - 1 - it) : it;

        if (it > 0) {
            uint32_t ba = buf ? bar1 : bar0;
            int      ph = buf ? ph1  : ph0;
            asm volatile(
                "{\n\t.reg .pred P;\n\t"
                "BW_%=:\n\t"
                "mbarrier.try_wait.parity.acquire.cta.shared::cta.b64 P, [%0], %1, 0x989680;\n\t"
                "@P bra.uni BWD_%=;\n\t"
                "bra.uni BW_%=;\n\t"
                "BWD_%=:\n\t}"
                :: "r"(ba), "r"(ph) : "memory");
            if (buf) ph1 ^= 1; else ph0 ^= 1;
        }

        // prefetch NEXT step's pre-activation (hidden behind this step)
        float gpn = 0.f;
        if (seg == 0 && it + 1 < T_LEN) {
            int tn = dir ? (T_LEN - 2 - it) : (it + 1);
            gpn = g_pre[dir][tn][grow];
        }

        // h . w on packed f32x2 (4 accumulator chains, conflict-free LDS)
        const ulonglong2* hp2 = (const ulonglong2*)(hbuf[buf] + seg * 68);
        uint64_t a0 = 0, a1 = 0, a2 = 0, a3 = 0;
        #pragma unroll
        for (int i = 0; i < 8; i++) {
            ulonglong2 hva = hp2[2*i];
            ulonglong2 hvb = hp2[2*i + 1];
            fma2(a0, w2[4*i],     hva.x);
            fma2(a1, w2[4*i + 1], hva.y);
            fma2(a2, w2[4*i + 2], hvb.x);
            fma2(a3, w2[4*i + 3], hvb.y);
        }
        float acc = (unpack_sum(a0) + unpack_sum(a1)) +
                    (unpack_sum(a2) + unpack_sum(a3));
        acc += __shfl_down_sync(0xffffffffu, acc, 2, 4);
        acc += __shfl_down_sync(0xffffffffu, acc, 1, 4);
        if (seg == 0) {
            float raw = acc + gp;
            gates[lr] = (gg == 2) ? hw_tanh(raw) : hw_sig(raw);
        }
        gp = gpn;

        // gates handoff: named barrier 1, 512 threads total.
        // Warps 1..15 arrive (non-blocking); updater warp 0 syncs.
        if (tid >= 32) {
            asm volatile("bar.arrive 1, 512;" ::: "memory");
        } else {
            asm volatile("bar.sync 1, 512;" ::: "memory");

            float I = gates[tid];
            float F = gates[32 + tid];
            float G = gates[64 + tid];
            float O = gates[96 + tid];
            creg = F * creg + I * G;
            float h = O * hw_tanh(creg);

            if (it < T_LEN - 1) {
                const uint32_t boff = (buf ^ 1) ? (uint32_t)HBUF_BYTES : 0u;  // next buffer
                uint32_t addr = ha_base + boff;
                #pragma unroll
                for (int r = 0; r < 8; r++) {
                    asm volatile("st.shared::cluster.f32 [%0], %1;"
                                 :: "r"(addr), "f"(h) : "memory");
                    addr += ha_step;
                }
                __syncwarp();
                if (tid < 8) {
                    // NO fence: stores-then-ARRIVE ordering validated (r13).
                    uint32_t ba = rb + ((buf ^ 1) ? 8u : 0u);
                    asm volatile(
                        "mbarrier.arrive.relaxed.cluster.shared::cluster.b64 _, [%0];"
                        :: "r"(ba) : "memory");
                }
            }
            g_hs[dir][t][(int)rank * 32 + tid] = h;
        }
    }
}

// ========================================================= Phase 3: feats
__global__ void feats_kernel(const float* __restrict__ Wlin,
                             const float* __restrict__ blin)
{
    __shared__ float Wl[C_TAGS][512];
    const int tid = threadIdx.x;
    for (int i = tid; i < C_TAGS * 512; i += 256)
        Wl[i >> 9][i & 511] = Wlin[i];
    __syncthreads();

    const int warp = tid >> 5, lane = tid & 31;
    const int t = blockIdx.x * 8 + warp;

    float hv[16];
    #pragma unroll
    for (int i = 0; i < 8; i++) hv[i]     = g_hs[0][t][lane + 32 * i];
    #pragma unroll
    for (int i = 0; i < 8; i++) hv[8 + i] = g_hs[1][t][lane + 32 * i];

    #pragma unroll
    for (int c = 0; c < C_TAGS; c++) {
        float a = 0.f;
        #pragma unroll
        for (int i = 0; i < 16; i++)
            a += hv[i] * Wl[c][lane + 32 * i];
        #pragma unroll
        for (int o = 16; o; o >>= 1)
            a += __shfl_down_sync(0xffffffffu, a, o);
        if (lane == 0) g_feats[t][c] = a + blin[c];
    }
}

// ================================================ Phase 4: Viterbi + trace
__global__ void viterbi_kernel(const float* __restrict__ trans,
                               float* __restrict__ out, int out_size)
{
    __shared__ uint8_t bps[T_LEN][C_TAGS];   // 24 KB
    __shared__ float   fvs[2][16];           // double-buffered: 1 syncwarp/step

    const int lane = threadIdx.x;
    float tr[C_TAGS];
    if (lane < C_TAGS) {
        #pragma unroll
        for (int p = 0; p < C_TAGS; p++) tr[p] = trans[lane * C_TAGS + p];
    }
    float fv = (lane == START_TAG) ? 0.f : NEGV;

    auto featload = [&](int idx) -> float {
        return (lane < C_TAGS && idx < T_LEN) ? g_feats[idx][lane] : 0.f;
    };
    auto vstep = [&](int t, float ft) {
        const int cb = t & 1;
        if (lane < C_TAGS) fvs[cb][lane] = fv;
        __syncwarp();
        if (lane < C_TAGS) {
            float s[C_TAGS];
            #pragma unroll
            for (int p = 0; p < C_TAGS; p++) s[p] = fvs[cb][p] + tr[p];
            float m01 = fmaxf(s[0], s[1]),  m23 = fmaxf(s[2], s[3]);
            float m45 = fmaxf(s[4], s[5]),  m67 = fmaxf(s[6], s[7]);
            float m89 = fmaxf(s[8], s[9]),  mab = fmaxf(s[10], s[11]);
            float best = fmaxf(fmaxf(fmaxf(m01, m23), fmaxf(m45, m67)),
                               fmaxf(m89, mab));
            unsigned mask = 0;
            #pragma unroll
            for (int p = 0; p < C_TAGS; p++)
                mask |= (s[p] == best) ? (1u << p) : 0u;
            bps[t][lane] = (uint8_t)(__ffs(mask) - 1);
            fv = best + ft;
        }
    };

    float f0 = featload(0), f1 = featload(1), f2 = featload(2), f3 = featload(3);
    for (int t = 0; t < T_LEN; t += 4) {
        float n0 = featload(t + 4), n1 = featload(t + 5);
        float n2 = featload(t + 6), n3 = featload(t + 7);
        vstep(t + 0, f0);
        vstep(t + 1, f1);
        vstep(t + 2, f2);
        vstep(t + 3, f3);
        f0 = n0; f1 = n1; f2 = n2; f3 = n3;
    }

    if (lane < C_TAGS) fvs[0][lane] = fv + trans[STOP_TAG * C_TAGS + lane];
    __syncwarp();

    if (lane == 0) {
        float best = fvs[0][0]; int bt = 0;
        #pragma unroll
        for (int p = 1; p < C_TAGS; p++)
            if (fvs[0][p] > best) { best = fvs[0][p]; bt = p; }

        if (out_size >= 1) out[0] = best;
        if (out_size >= T_LEN + 1) {
            int tag = bt;
            for (int t = T_LEN - 1; t >= 1; t--) {
                out[1 + t] = (float)tag;
                tag = bps[t][tag];
            }
            out[1] = (float)tag;
        }
    }
}

// ================================================================= launch
extern "C" void kernel_launch(void* const* d_in, const int* in_sizes, int n_in,
                              void* d_out, int out_size)
{
    const int*   sent   = (const int*)  d_in[0];
    const float* emb    = (const float*)d_in[1];
    const float* Wih_f  = (const float*)d_in[2];
    const float* Whh_f  = (const float*)d_in[3];
    const float* bih_f  = (const float*)d_in[4];
    const float* bhh_f  = (const float*)d_in[5];
    const float* Wih_b  = (const float*)d_in[6];
    const float* Whh_b  = (const float*)d_in[7];
    const float* bih_b  = (const float*)d_in[8];
    const float* bhh_b  = (const float*)d_in[9];
    const float* Wlin   = (const float*)d_in[10];
    const float* blin   = (const float*)d_in[11];
    const float* h0     = (const float*)d_in[12];
    const float* c0     = (const float*)d_in[13];
    const float* transi = (const float*)d_in[14];
    float* out = (float*)d_out;

    // two dummy launches keep ncu's fixed capture slot on lstm_rec
    nop_kernel<<<1, 1>>>();
    nop_kernel<<<1, 1>>>();

    gates_gemm<<<dim3(T_LEN / 32, G4 / 32, 2), 256>>>(
        sent, emb, Wih_f, bih_f, bhh_f, Wih_b, bih_b, bhh_b);

    lstm_rec<<<16, 512>>>(Whh_f, Whh_b, h0, c0);

    feats_kernel<<<T_LEN / 8, 256>>>(Wlin, blin);

    viterbi_kernel<<<1, 32>>>(transi, out, out_size);
}

// round 17
// speedup vs baseline: 2.1510x; 1.2324x over previous
#include <cuda_runtime.h>
#include <cuda_bf16.h>
#include <cstdint>

#define T_LEN 2048
#define EMB   256
#define H2    256
#define G4    1024
#define C_TAGS 12
#define NEGV  (-10000.0f)
#define START_TAG 10
#define STOP_TAG  11

#define CLUSTER_N 16
// h layout: 16 blocks of 16 floats; block b at float offset b*20 + (b>>2)*4
// -> every 16B chunk is 16B-aligned; the 4 per-seg bases (s*84 floats) hit
// banks {0,20,8,28} -> conflict-free broadcast LDS.128.
#define HPAD 336            // floats per h buffer (15*20+3*4+16 padded)
#define HBUF_BYTES 1344     // HPAD * 4

__device__ __forceinline__ int hblk_off(int b) { return b * 20 + (b >> 2) * 4; }

// ---------------------------------------------------------------- scratch
__device__ float g_pre[2][T_LEN][G4];    // 16 MB: gate pre-activations
__device__ float g_hs[2][T_LEN][H2];     // 4 MB: hidden states per direction
__device__ float g_feats[T_LEN][C_TAGS]; // 96 KB

__device__ __forceinline__ uint32_t smem_u32(const void* p) {
    return (uint32_t)__cvta_generic_to_shared(p);
}

// HW tanh (sm_75+): single MUFU op
__device__ __forceinline__ float hw_tanh(float x) {
    float r;
    asm("tanh.approx.f32 %0, %1;" : "=f"(r) : "f"(x));
    return r;
}
__device__ __forceinline__ float hw_sig(float x) {
    return fmaf(0.5f, hw_tanh(0.5f * x), 0.5f);
}

__device__ __forceinline__ void fma2(uint64_t& d, uint64_t a, uint64_t b) {
    asm("fma.rn.f32x2 %0, %1, %2, %0;" : "+l"(d) : "l"(a), "l"(b));
}
__device__ __forceinline__ float unpack_sum(uint64_t a) {
    float lo, hi;
    asm("mov.b64 {%0, %1}, %2;" : "=f"(lo), "=f"(hi) : "l"(a));
    return lo + hi;
}

// dummy kernel: shifts ncu's fixed capture slot onto lstm_rec
__global__ void nop_kernel() {}

// ============================================================ Phase 1: GEMM
__global__ void gates_gemm(const int* __restrict__ sent,
                           const float* __restrict__ emb,
                           const float* __restrict__ Wih_f,
                           const float* __restrict__ bih_f,
                           const float* __restrict__ bhh_f,
                           const float* __restrict__ Wih_b,
                           const float* __restrict__ bih_b,
                           const float* __restrict__ bhh_b)
{
    const int dir = blockIdx.z;
    const float* Wih = dir ? Wih_b : Wih_f;
    const float* bih = dir ? bih_b : bih_f;
    const float* bhh = dir ? bhh_b : bhh_f;
    const int t0 = blockIdx.x * 32;
    const int r0 = blockIdx.y * 32;
    const int tid = threadIdx.x;
    const int lane = tid & 31;
    const int warp = tid >> 5;

    __shared__ float Xs[32][33];
    __shared__ float Ws[32][33];
    __shared__ int   sidx[32];

    if (tid < 32) sidx[tid] = sent[t0 + tid];
    __syncthreads();

    float acc[4] = {0.f, 0.f, 0.f, 0.f};
    for (int kc = 0; kc < EMB; kc += 32) {
        #pragma unroll
        for (int e = 0; e < 4; e++) {
            int idx = tid + 256 * e;
            int a = idx >> 5, b = idx & 31;
            Xs[a][b] = emb[(long long)sidx[a] * EMB + kc + b];
            Ws[a][b] = Wih[(r0 + a) * EMB + kc + b];
        }
        __syncthreads();
        #pragma unroll
        for (int k = 0; k < 32; k++) {
            float wk = Ws[lane][k];
            #pragma unroll
            for (int e = 0; e < 4; e++)
                acc[e] += Xs[warp + 8 * e][k] * wk;
        }
        __syncthreads();
    }
    float bias = bih[r0 + lane] + bhh[r0 + lane];
    #pragma unroll
    for (int e = 0; e < 4; e++)
        g_pre[dir][t0 + warp + 8 * e][r0 + lane] = acc[e] + bias;
}

// ====================================================== Phase 2: recurrence
// 2 clusters of SIXTEEN CTAs (one per direction), 256 threads each.
// CTA rank owns h[16r..16r+16) and gate rows {g*256 + 16r + j}. Per-SMSP
// FFMA2 issue and LDS wavefronts HALVE vs the 8-CTA version. Protocol is
// the r16 winner unchanged: named-bar gates hop, fence-free remote stores
// then relaxed arrives (r13-validated ordering), acquire.cta waits.
__global__ void __cluster_dims__(CLUSTER_N, 1, 1) __launch_bounds__(256, 1)
lstm_rec(const float* __restrict__ Whh_f,
         const float* __restrict__ Whh_b,
         const float* __restrict__ h0,
         const float* __restrict__ c0)
{
    const int dir  = blockIdx.x >> 4;
    unsigned rank;
    asm("mov.u32 %0, %%cluster_ctarank;" : "=r"(rank));
    const float* Whh = dir ? Whh_b : Whh_f;

    const int tid = threadIdx.x;
    const int lr  = tid >> 2;     // local gate row 0..63
    const int seg = tid & 3;      // 64-col segment
    const int gg  = lr >> 4;      // gate id 0..3 (i,f,g,o)
    const int jj  = lr & 15;      // h index within CTA
    const int grow = (gg << 8) + (int)(rank << 4) + jj;

    __shared__ __align__(16) float hbuf[2][HPAD];
    __shared__ float    gates[64];
    __shared__ uint64_t bars[2];                  // bars[1] = bars[0] + 8B

    // weights -> packed f32x2 registers (64 cols of my gate row)
    uint64_t w2[32];
    {
        const ulonglong2* wp = (const ulonglong2*)(Whh + grow * H2 + seg * 64);
        #pragma unroll
        for (int i = 0; i < 16; i++) {
            ulonglong2 v = wp[i];
            w2[2*i] = v.x; w2[2*i+1] = v.y;
        }
    }

    // init h (blocked layout), c, barriers
    if (tid < H2) hbuf[0][hblk_off(tid >> 4) + (tid & 15)] = h0[dir * H2 + tid];
    float creg = 0.f;
    if (tid < 16) creg = c0[dir * H2 + (int)rank * 16 + tid];

    const uint32_t bar0 = smem_u32(&bars[0]);
    const uint32_t bar1 = smem_u32(&bars[1]);
    if (tid == 0) {
        asm volatile("mbarrier.init.shared.b64 [%0], %1;" :: "r"(bar0), "r"(CLUSTER_N) : "memory");
        asm volatile("mbarrier.init.shared.b64 [%0], %1;" :: "r"(bar1), "r"(CLUSTER_N) : "memory");
    }
    __syncthreads();
    asm volatile("barrier.cluster.arrive.aligned;" ::: "memory");
    asm volatile("barrier.cluster.wait.aligned;"  ::: "memory");

    // updater remote addressing: base + r*stride
    uint32_t ha_base = 0, ha_step = 0, rb = 0;
    if (tid < 16) {
        uint32_t loc0 = smem_u32(&hbuf[0][hblk_off((int)rank) + tid]);
        uint32_t a0, a1;
        asm("mapa.shared::cluster.u32 %0, %1, %2;" : "=r"(a0) : "r"(loc0), "r"(0));
        asm("mapa.shared::cluster.u32 %0, %1, %2;" : "=r"(a1) : "r"(loc0), "r"(1));
        ha_base = a0; ha_step = a1 - a0;
        asm("mapa.shared::cluster.u32 %0, %1, %2;" : "=r"(rb) : "r"(bar0), "r"(tid));
    }

    int ph0 = 0, ph1 = 0;

    // pre-load step-0 pre-activation
    float gp = 0.f;
    if (seg == 0) gp = g_pre[dir][dir ? (T_LEN - 1) : 0][grow];

    for (int it = 0; it < T_LEN; it++) {
        const int buf = it & 1;
        const int t = dir ? (T_LEN - 1 - it) : it;

        if (it > 0) {
            uint32_t ba = buf ? bar1 : bar0;
            int      ph = buf ? ph1  : ph0;
            asm volatile(
                "{\n\t.reg .pred P;\n\t"
                "BW_%=:\n\t"
                "mbarrier.try_wait.parity.acquire.cta.shared::cta.b64 P, [%0], %1, 0x989680;\n\t"
                "@P bra.uni BWD_%=;\n\t"
                "bra.uni BW_%=;\n\t"
                "BWD_%=:\n\t}"
                :: "r"(ba), "r"(ph) : "memory");
            if (buf) ph1 ^= 1; else ph0 ^= 1;
        }

        // prefetch NEXT step's pre-activation
        float gpn = 0.f;
        if (seg == 0 && it + 1 < T_LEN) {
            int tn = dir ? (T_LEN - 2 - it) : (it + 1);
            gpn = g_pre[dir][tn][grow];
        }

        // 64-col dot: seg covers h blocks 4seg..4seg+3 (base s*84 floats)
        const float* hb = hbuf[buf] + seg * 84;
        uint64_t a0 = 0, a1 = 0, a2 = 0, a3 = 0;
        #pragma unroll
        for (int b = 0; b < 4; b++) {
            const ulonglong2* p = (const ulonglong2*)(hb + b * 20);
            ulonglong2 v0 = p[0];
            ulonglong2 v1 = p[1];
            ulonglong2 v2 = p[2];
            ulonglong2 v3 = p[3];
            fma2(a0, w2[b*8 + 0], v0.x);
            fma2(a1, w2[b*8 + 1], v0.y);
            fma2(a2, w2[b*8 + 2], v1.x);
            fma2(a3, w2[b*8 + 3], v1.y);
            fma2(a0, w2[b*8 + 4], v2.x);
            fma2(a1, w2[b*8 + 5], v2.y);
            fma2(a2, w2[b*8 + 6], v3.x);
            fma2(a3, w2[b*8 + 7], v3.y);
        }
        float acc = (unpack_sum(a0) + unpack_sum(a1)) +
                    (unpack_sum(a2) + unpack_sum(a3));
        acc += __shfl_down_sync(0xffffffffu, acc, 2, 4);
        acc += __shfl_down_sync(0xffffffffu, acc, 1, 4);
        if (seg == 0) {
            float raw = acc + gp;
            gates[lr] = (gg == 2) ? hw_tanh(raw) : hw_sig(raw);
        }
        gp = gpn;

        // gates handoff: named barrier 1, 256 threads.
        if (tid >= 32) {
            asm volatile("bar.arrive 1, 256;" ::: "memory");
        } else {
            asm volatile("bar.sync 1, 256;" ::: "memory");

            if (tid < 16) {
                float I = gates[tid];
                float F = gates[16 + tid];
                float G = gates[32 + tid];
                float O = gates[48 + tid];
                creg = F * creg + I * G;
                float h = O * hw_tanh(creg);

                if (it < T_LEN - 1) {
                    const uint32_t boff = (buf ^ 1) ? (uint32_t)HBUF_BYTES : 0u;
                    uint32_t addr = ha_base + boff;
                    #pragma unroll
                    for (int r = 0; r < CLUSTER_N; r++) {
                        asm volatile("st.shared::cluster.f32 [%0], %1;"
                                     :: "r"(addr), "f"(h) : "memory");
                        addr += ha_step;
                    }
                }
                g_hs[dir][t][(int)rank * 16 + tid] = h;
            }
            __syncwarp();
            if (tid < 16 && it < T_LEN - 1) {
                // fence-free: stores-then-ARRIVE ordering (r13-validated)
                uint32_t ba = rb + ((buf ^ 1) ? 8u : 0u);
                asm volatile(
                    "mbarrier.arrive.relaxed.cluster.shared::cluster.b64 _, [%0];"
                    :: "r"(ba) : "memory");
            }
        }
    }
}

// ========================================================= Phase 3: feats
__global__ void feats_kernel(const float* __restrict__ Wlin,
                             const float* __restrict__ blin)
{
    __shared__ float Wl[C_TAGS][512];
    const int tid = threadIdx.x;
    for (int i = tid; i < C_TAGS * 512; i += 256)
        Wl[i >> 9][i & 511] = Wlin[i];
    __syncthreads();

    const int warp = tid >> 5, lane = tid & 31;
    const int t = blockIdx.x * 8 + warp;

    float hv[16];
    #pragma unroll
    for (int i = 0; i < 8; i++) hv[i]     = g_hs[0][t][lane + 32 * i];
    #pragma unroll
    for (int i = 0; i < 8; i++) hv[8 + i] = g_hs[1][t][lane + 32 * i];

    #pragma unroll
    for (int c = 0; c < C_TAGS; c++) {
        float a = 0.f;
        #pragma unroll
        for (int i = 0; i < 16; i++)
            a += hv[i] * Wl[c][lane + 32 * i];
        #pragma unroll
        for (int o = 16; o; o >>= 1)
            a += __shfl_down_sync(0xffffffffu, a, o);
        if (lane == 0) g_feats[t][c] = a + blin[c];
    }
}

// ================================================ Phase 4: Viterbi + trace
__global__ void viterbi_kernel(const float* __restrict__ trans,
                               float* __restrict__ out, int out_size)
{
    __shared__ uint8_t bps[T_LEN][C_TAGS];   // 24 KB
    __shared__ float   fvs[2][16];

    const int lane = threadIdx.x;
    float tr[C_TAGS];
    if (lane < C_TAGS) {
        #pragma unroll
        for (int p = 0; p < C_TAGS; p++) tr[p] = trans[lane * C_TAGS + p];
    }
    float fv = (lane == START_TAG) ? 0.f : NEGV;

    auto featload = [&](int idx) -> float {
        return (lane < C_TAGS && idx < T_LEN) ? g_feats[idx][lane] : 0.f;
    };
    auto vstep = [&](int t, float ft) {
        const int cb = t & 1;
        if (lane < C_TAGS) fvs[cb][lane] = fv;
        __syncwarp();
        if (lane < C_TAGS) {
            float s[C_TAGS];
            #pragma unroll
            for (int p = 0; p < C_TAGS; p++) s[p] = fvs[cb][p] + tr[p];
            float m01 = fmaxf(s[0], s[1]),  m23 = fmaxf(s[2], s[3]);
            float m45 = fmaxf(s[4], s[5]),  m67 = fmaxf(s[6], s[7]);
            float m89 = fmaxf(s[8], s[9]),  mab = fmaxf(s[10], s[11]);
            float best = fmaxf(fmaxf(fmaxf(m01, m23), fmaxf(m45, m67)),
                               fmaxf(m89, mab));
            unsigned mask = 0;
            #pragma unroll
            for (int p = 0; p < C_TAGS; p++)
                mask |= (s[p] == best) ? (1u << p) : 0u;
            bps[t][lane] = (uint8_t)(__ffs(mask) - 1);
            fv = best + ft;
        }
    };

    float f0 = featload(0), f1 = featload(1), f2 = featload(2), f3 = featload(3);
    for (int t = 0; t < T_LEN; t += 4) {
        float n0 = featload(t + 4), n1 = featload(t + 5);
        float n2 = featload(t + 6), n3 = featload(t + 7);
        vstep(t + 0, f0);
        vstep(t + 1, f1);
        vstep(t + 2, f2);
        vstep(t + 3, f3);
        f0 = n0; f1 = n1; f2 = n2; f3 = n3;
    }

    if (lane < C_TAGS) fvs[0][lane] = fv + trans[STOP_TAG * C_TAGS + lane];
    __syncwarp();

    if (lane == 0) {
        float best = fvs[0][0]; int bt = 0;
        #pragma unroll
        for (int p = 1; p < C_TAGS; p++)
            if (fvs[0][p] > best) { best = fvs[0][p]; bt = p; }

        if (out_size >= 1) out[0] = best;
        if (out_size >= T_LEN + 1) {
            int tag = bt;
            for (int t = T_LEN - 1; t >= 1; t--) {
                out[1 + t] = (float)tag;
                tag = bps[t][tag];
            }
            out[1] = (float)tag;
        }
    }
}

// ================================================================= launch
extern "C" void kernel_launch(void* const* d_in, const int* in_sizes, int n_in,
                              void* d_out, int out_size)
{
    const int*   sent   = (const int*)  d_in[0];
    const float* emb    = (const float*)d_in[1];
    const float* Wih_f  = (const float*)d_in[2];
    const float* Whh_f  = (const float*)d_in[3];
    const float* bih_f  = (const float*)d_in[4];
    const float* bhh_f  = (const float*)d_in[5];
    const float* Wih_b  = (const float*)d_in[6];
    const float* Whh_b  = (const float*)d_in[7];
    const float* bih_b  = (const float*)d_in[8];
    const float* bhh_b  = (const float*)d_in[9];
    const float* Wlin   = (const float*)d_in[10];
    const float* blin   = (const float*)d_in[11];
    const float* h0     = (const float*)d_in[12];
    const float* c0     = (const float*)d_in[13];
    const float* transi = (const float*)d_in[14];
    float* out = (float*)d_out;

    // 16-CTA clusters are non-portable: enable explicitly (host-side
    // attribute set, not a stream op — safe under graph capture)
    cudaFuncSetAttribute(lstm_rec,
                         cudaFuncAttributeNonPortableClusterSizeAllowed, 1);

    // two dummy launches keep ncu's fixed capture slot on lstm_rec
    nop_kernel<<<1, 1>>>();
    nop_kernel<<<1, 1>>>();

    gates_gemm<<<dim3(T_LEN / 32, G4 / 32, 2), 256>>>(
        sent, emb, Wih_f, bih_f, bhh_f, Wih_b, bih_b, bhh_b);

    lstm_rec<<<32, 256>>>(Whh_f, Whh_b, h0, c0);

    feats_kernel<<<T_LEN / 8, 256>>>(Wlin, blin);

    viterbi_kernel<<<1, 32>>>(transi, out, out_size);
}